// round 7
// baseline (speedup 1.0000x reference)
#include <cuda_runtime.h>
#include <stdint.h>

#define NB 32
#define NT 15
#define C1F 30                      // filters per conv1 block (90 = 3*30)

// ---------------- device scratch (no cudaMalloc allowed) ----------------
static __device__ __align__(16) int8_t  g_ft1p[NB*90*15*16];   // pooled L1, row-stride 16
static __device__              uint8_t g_cflag1[NB*90];
static __device__              int     g_any1[NB];
static __device__ __align__(16) int8_t  g_ft2p[NB*250*16];     // pooled L2 fire times
static __device__              uint8_t g_cflag2[NB*250];
static __device__              int     g_any2[NB];
static __device__              float   g_wsat2[250*36];        // SAT of channel-summed w2
static __device__              float   g_wsat3[200*36];        // SAT of channel-summed w3
static __device__              unsigned long long g_best[NB];  // winner keys
static __device__              int     g_done[NB];             // conv3 block counters

extern __shared__ unsigned char smem_raw[];

// ===========================================================================
// k_prep: weight SATs (deterministic tree) + flag/best/done zeroing.
// Blocks: [0,250) wsat2 | [250,450) wsat3 | 450 zero.
__global__ __launch_bounds__(256) void k_prep(const float* __restrict__ w2,
                                              const float* __restrict__ w3) {
    int bid = blockIdx.x, tid = threadIdx.x;
    if (bid < 450) {
        __shared__ float s_part[250];
        __shared__ float s25[25];
        const float* src; int C; float* dst; int f;
        if (bid < 250) { f = bid;     src = w2; C = 90;  dst = g_wsat2 + f*36; }
        else           { f = bid-250; src = w3; C = 250; dst = g_wsat3 + f*36; }
        if (tid < 250) {
            int p = tid / 10, g = tid % 10;
            float s = 0.0f;
            for (int c = g; c < C; c += 10) s += src[((size_t)f*C + c)*25 + p];
            s_part[p*10 + g] = s;
        }
        __syncthreads();
        if (tid < 25) {
            float s = 0.0f;
            for (int g = 0; g < 10; g++) s += s_part[tid*10 + g];
            s25[tid] = s;
        }
        __syncthreads();
        if (tid < 36) {
            int i = tid / 6, j = tid % 6;
            float s = 0.0f;
            for (int ii = 0; ii < i; ii++)
                for (int jj = 0; jj < j; jj++) s += s25[ii*5 + jj];
            dst[tid] = s;
        }
    } else {
        for (int i = tid; i < NB*90;  i += 256) g_cflag1[i] = 0;
        for (int i = tid; i < NB*250; i += 256) g_cflag2[i] = 0;
        if (tid < NB) {
            g_any1[tid] = 0; g_any2[tid] = 0;
            g_best[tid] = 0ull; g_done[tid] = 0;
        }
    }
}

// ===========================================================================
// conv1 slow path (essentially never taken): per-t rescan straight from input.
__device__ __noinline__ int conv1_slow(const float* __restrict__ inp,
                                       int b, int f, int y, int x,
                                       const float* __restrict__ w1) {
    const float* wf = w1 + (size_t)f*882;
    for (int t = 1; t < 15; t++) {
        const float* pl = inp + ((size_t)(b*NT + t))*18*1024;
        float cum = 0.0f;
        for (int c = 0; c < 18; c++)
            for (int i = 0; i < 7; i++) {
                int h = y + i - 2;
                if ((unsigned)h >= 32u) continue;
                for (int j = 0; j < 7; j++) {
                    int w = x + j - 2;
                    if ((unsigned)w >= 32u) continue;
                    if (pl[(c << 10) + (h << 5) + w] > 0.5f) cum += wf[c*49 + i*7 + j];
                }
            }
        if (cum > 15.0f) return t;
    }
    return 15;
}

// ===========================================================================
// conv1: lane=filter (30/warp), warp = 4 adjacent x, 1 row per warp. Weights
// transposed in-kernel from w1 (warp=filter, coalesced). 108.5KB smem => 2
// blocks/SM. Masks from t=0 plane. Fused 2x2 pool + flags.
// grid (8 row-quads, 3 fgroups, NB), 1024 threads.
#define CONV1_SMEM (882*C1F*4 + 18*10*8 + 4*32*C1F)
__global__ __launch_bounds__(1024) void k_conv1(const float* __restrict__ inp,
                                                const float* __restrict__ w1) {
    float*    s_w  = (float*)smem_raw;                              // 105840 B
    uint64_t* s_m  = (uint64_t*)(smem_raw + 882*C1F*4);             // [18][10]
    int8_t*   s_ft = (int8_t*)(smem_raw + 882*C1F*4 + 18*10*8);     // [4r][32x][30f]
    int tid = threadIdx.x;
    int rq = blockIdx.x, fg = blockIdx.y, b = blockIdx.z;
    int lane = tid & 31, w = tid >> 5;
    int dy = w >> 3, q = w & 7, x0 = q*4;

    // transpose-load weights: warp w (w<30) owns filter fg*30+w
    if (w < C1F) {
        const float* wf = w1 + (size_t)(fg*C1F + w)*882;
        for (int k = lane; k < 882; k += 32)
            s_w[k*C1F + w] = wf[k];
    }
    // row bitmasks from the t=0 plane: bit (w_in+2) set iff input fires at t=0
    if (tid < 180) {
        int c = tid / 10, rr = tid % 10;
        int h = rq*4 + rr - 2;
        uint64_t mask = 0;
        if ((unsigned)h < 32u) {
            const float4* row = (const float4*)(inp + ((size_t)b*NT*18 + c)*1024 + (h << 5));
            uint32_t bits = 0;
#pragma unroll
            for (int k = 0; k < 8; k++) {
                float4 v = row[k];
                bits |= (v.x > 0.5f ? 1u : 0u) << (k*4);
                bits |= (v.y > 0.5f ? 2u : 0u) << (k*4);
                bits |= (v.z > 0.5f ? 4u : 0u) << (k*4);
                bits |= (v.w > 0.5f ? 8u : 0u) << (k*4);
            }
            mask = ((uint64_t)bits) << 2;
        }
        s_m[c*10 + rr] = mask;
    }
    __syncthreads();

    int y = rq*4 + dy;
    float a0 = 0.f, a1 = 0.f, a2 = 0.f, a3 = 0.f;
    if (y < 30 && lane < C1F) {
        for (int c = 0; c < 18; c++) {
            const uint64_t* mrow = s_m + c*10 + dy;
            const float* wc = s_w + c*49*C1F + lane;
#pragma unroll
            for (int i = 0; i < 7; i++) {
                uint32_t wnd = (uint32_t)(mrow[i] >> x0) & 0x3FFu;
                const float* wi = wc + i*7*C1F;
                while (wnd) {
                    int p = __ffs(wnd) - 1;
                    wnd &= wnd - 1;
                    const float* wp = wi + p*C1F;
                    if (p <= 6)           a0 += wp[0];
                    if (p >= 1 && p <= 7) a1 += wp[-C1F];
                    if (p >= 2 && p <= 8) a2 += wp[-2*C1F];
                    if (p >= 3)           a3 += wp[-3*C1F];
                }
            }
        }
    }
    if (lane < C1F) {
        int f = fg*C1F + lane;
        float aa[4] = {a0, a1, a2, a3};
#pragma unroll
        for (int k = 0; k < 4; k++) {
            int xx = x0 + k;
            int ft = 0;
            if (y < 30 && xx < 30)
                ft = (aa[k] > 15.0f) ? 0 : conv1_slow(inp, b, f, y, xx, w1);
            s_ft[(dy*32 + xx)*C1F + lane] = (int8_t)ft;
        }
    }
    __syncthreads();

    // fused 2x2 min-pool + channel flags (2 pooled rows per block)
    bool nz = false;
    if (tid < 900) {
        int pf = tid % C1F;
        int rest = tid / C1F;               // 0..29
        int pcol = rest % 15;
        int pr   = rest / 15;               // 0..1
        int prow = rq*2 + pr;
        int r0 = pr*2, c0 = pcol*2;
        int v0 = s_ft[(r0*32     + c0  )*C1F + pf];
        int v1 = s_ft[(r0*32     + c0+1)*C1F + pf];
        int v2 = s_ft[((r0+1)*32 + c0  )*C1F + pf];
        int v3 = s_ft[((r0+1)*32 + c0+1)*C1F + pf];
        int m0 = v0 < v1 ? v0 : v1;
        int m1 = v2 < v3 ? v2 : v3;
        int pv = m0 < m1 ? m0 : m1;
        int ff = fg*C1F + pf;
        if (prow < 15) {
            g_ft1p[((b*90 + ff)*15 + prow)*16 + pcol] = (int8_t)pv;
            if (pv) { g_cflag1[b*90 + ff] = 1; nz = true; }
        }
    }
    int cnt = __syncthreads_count(nz);
    if (tid == 0 && cnt) atomicAdd(&g_any1[b], 1);
}

// ===========================================================================
// conv2: 32 filters per block, 512 threads. SAT fast path; slow path uses a
// deterministic compacted channel list + def[15] registers, reading flagged
// rows straight from global. Fused 3x3 pool + layer-2 flags.
__global__ __launch_bounds__(512) void k_conv2(const float* __restrict__ w2) {
    __shared__ float   s_sat[32*36];
    __shared__ int8_t  s_ftp[32*169];
    __shared__ uint8_t s_list[90];
    __shared__ int     s_cnt;
    int tid = threadIdx.x;
    int chunk = blockIdx.x, b = blockIdx.y;
    int f0 = chunk*32;
    int nf = (chunk == 7) ? 26 : 32;
    int any = g_any1[b];

    for (int i = tid; i < nf*36; i += 512) s_sat[i] = g_wsat2[(f0 + i/36)*36 + i%36];
    if (any && tid < 32) {
        int base = 0;
#pragma unroll
        for (int g = 0; g < 3; g++) {
            int c = g*32 + tid;
            bool flag = (c < 90) && g_cflag1[b*90 + c];
            unsigned ball = __ballot_sync(0xFFFFFFFFu, flag);
            if (flag) s_list[base + __popc(ball & ((1u << tid) - 1u))] = (uint8_t)c;
            base += __popc(ball);
        }
        if (tid == 0) s_cnt = base;
    }
    __syncthreads();

    int ncorr = any ? s_cnt : 0;
    for (int o = tid; o < nf*169; o += 512) {
        int fi = o / 169, pix = o - fi*169;
        int y = pix / 13, x = pix - y*13;
        int r0 = max(0, y-1), r1 = min(14, y+3);
        int c0 = max(0, x-1), c1 = min(14, x+3);
        int i0 = r0 - (y-1), i1 = r1 - (y-1);
        int j0 = c0 - (x-1), j1 = c1 - (x-1);
        const float* S = s_sat + fi*36;
        float a0 = S[(i1+1)*6 + (j1+1)] - S[i0*6 + (j1+1)]
                 - S[(i1+1)*6 + j0]     + S[i0*6 + j0];
        int ft;
        if (!ncorr) {
            ft = (a0 > 10.0f) ? 0 : 15;
        } else {
            float def[15];
#pragma unroll
            for (int t = 0; t < 15; t++) def[t] = 0.f;
            for (int li = 0; li < ncorr; li++) {
                int c = s_list[li];
                const int8_t* tp = g_ft1p + ((size_t)(b*90 + c)*15)*16;
                const float*  wp = w2 + ((size_t)(f0+fi)*90 + c)*25;
                for (int r = r0; r <= r1; r++)
                    for (int cc = c0; cc <= c1; cc++) {
                        int tf = tp[r*16 + cc];
                        if (tf) {
                            float wv = __ldg(wp + (r-(y-1))*5 + (cc-(x-1)));
#pragma unroll
                            for (int t = 0; t < 15; t++) def[t] += (tf > t) ? wv : 0.f;
                        }
                    }
            }
            ft = 15;
#pragma unroll
            for (int t = 14; t >= 0; t--) if (a0 - def[t] > 10.0f) ft = t;
        }
        s_ftp[fi*169 + pix] = (int8_t)ft;
    }
    __syncthreads();

    // 3x3 s3 min-pool + flags
    bool nz = false;
    for (int i = tid; i < nf*16; i += 512) {
        int fi = i >> 4, p = i & 15;
        int y = (p >> 2)*3, x = (p & 3)*3;
        const int8_t* bp = s_ftp + fi*169 + y*13 + x;
        int v = 15;
#pragma unroll
        for (int dy = 0; dy < 3; dy++)
#pragma unroll
            for (int dx = 0; dx < 3; dx++) {
                int u = bp[dy*13 + dx];
                v = u < v ? u : v;
            }
        g_ft2p[(b*250 + f0 + fi)*16 + p] = (int8_t)v;
        if (v) { g_cflag2[b*250 + f0 + fi] = 1; nz = true; }
    }
    int cnt = __syncthreads_count(nz);
    if (tid == 0 && cnt) atomicAdd(&g_any2[b], 1);
}

// ===========================================================================
// conv3: SAT fast path; slow path via compacted list + def[15] registers
// (direct global reads). Fused winner (atomicMax keys) + last-block decode.
__global__ __launch_bounds__(256) void k_conv3(const float* __restrict__ w3,
                                               float* __restrict__ pot,
                                               float* __restrict__ cls) {
    __shared__ float   s_sat[16*36];
    __shared__ uint8_t s_list[250];
    __shared__ int     s_cnt;
    __shared__ unsigned long long s_k[256];
    int tid = threadIdx.x;
    int fg = blockIdx.x, b = blockIdx.y;
    int any = g_any2[b];

    for (int i = tid; i < 16*36; i += 256) {
        int f = fg*16 + i/36;
        s_sat[i] = (f < 200) ? g_wsat3[f*36 + i%36] : 0.0f;
    }
    if (any && tid < 32) {
        int base = 0;
#pragma unroll
        for (int g = 0; g < 8; g++) {
            int c = g*32 + tid;
            bool flag = (c < 250) && g_cflag2[b*250 + c];
            unsigned ball = __ballot_sync(0xFFFFFFFFu, flag);
            if (flag) s_list[base + __popc(ball & ((1u << tid) - 1u))] = (uint8_t)(c);
            base += __popc(ball);
        }
        if (tid == 0) s_cnt = base;
    }
    __syncthreads();

    int ncorr = any ? s_cnt : 0;
    int fi = tid >> 4, p = tid & 15;
    int f = fg*16 + fi;
    unsigned long long key = 0ull;
    if (f < 200) {
        int y = p >> 2, x = p & 3;
        int r0 = max(0, y-2), r1 = min(3, y+2);
        int c0 = max(0, x-2), c1 = min(3, x+2);
        int i0 = r0 - (y-2), i1 = r1 - (y-2);
        int j0 = c0 - (x-2), j1 = c1 - (x-2);
        const float* S = s_sat + fi*36;
        float a0 = S[(i1+1)*6 + (j1+1)] - S[i0*6 + (j1+1)]
                 - S[(i1+1)*6 + j0]     + S[i0*6 + j0];
        float* o = pot + ((size_t)b*NT*200 + f)*16 + p;
        float last;
        if (!ncorr) {
#pragma unroll
            for (int t = 0; t < NT; t++) o[(size_t)t * 3200] = a0;
            last = a0;
        } else {
            float def[15];
#pragma unroll
            for (int t = 0; t < 15; t++) def[t] = 0.f;
            for (int li = 0; li < ncorr; li++) {
                int c = s_list[li];
                const int8_t* tp = g_ft2p + (size_t)(b*250 + c)*16;
                const float*  wp = w3 + ((size_t)f*250 + c)*25;
                for (int r = r0; r <= r1; r++)
                    for (int cc = c0; cc <= c1; cc++) {
                        int tf = tp[r*4 + cc];
                        if (tf) {
                            float wv = __ldg(wp + (r-(y-2))*5 + (cc-(x-2)));
#pragma unroll
                            for (int t = 0; t < 15; t++) def[t] += (tf > t) ? wv : 0.f;
                        }
                    }
            }
#pragma unroll
            for (int t = 0; t < NT; t++) o[(size_t)t * 3200] = a0 - def[t];
            last = a0 - def[14];
        }
        if (last > 0.0f)
            key = ((unsigned long long)__float_as_uint(last) << 32)
                | (unsigned)(~(f*16 + p));
    }
    s_k[tid] = key;
    __syncthreads();
    for (int s = 128; s > 0; s >>= 1) {
        if (tid < s) {
            unsigned long long o2 = s_k[tid+s];
            if (o2 > s_k[tid]) s_k[tid] = o2;
        }
        __syncthreads();
    }
    if (tid == 0) {
        if (s_k[0]) atomicMax(&g_best[b], s_k[0]);
        __threadfence();
        int d = atomicAdd(&g_done[b], 1);
        if (d == 12 && cls) {               // last of 13 blocks for batch b
            __threadfence();
            unsigned long long bestk = g_best[b];
            if (bestk == 0ull) cls[b] = -1.0f;
            else {
                unsigned idx = ~(unsigned)(bestk & 0xFFFFFFFFu);
                cls[b] = (float)((idx >> 4) / 20);
            }
        }
    }
}

// ===========================================================================
extern "C" void kernel_launch(void* const* d_in, const int* in_sizes, int n_in,
                              void* d_out, int out_size) {
    const float* inp = (const float*)d_in[0];
    const float* w1  = (const float*)d_in[1];
    const float* w2  = (const float*)d_in[2];
    const float* w3  = (const float*)d_in[3];

    float* out = (float*)d_out;
    float* pot = out;
    float* cls = nullptr;
    if (out_size == NB + NB*NT*3200) {   // (cls, pot3) concatenated
        cls = out;
        pot = out + NB;
    }

    static bool attr_set = false;
    if (!attr_set) {
        cudaFuncSetAttribute(k_conv1, cudaFuncAttributeMaxDynamicSharedMemorySize,
                             CONV1_SMEM);
        attr_set = true;
    }

    k_prep <<<451, 256>>>(w2, w3);
    k_conv1<<<dim3(8, 3, NB), 1024, CONV1_SMEM>>>(inp, w1);
    k_conv2<<<dim3(8, NB), 512>>>(w2);
    k_conv3<<<dim3(13, NB), 256>>>(w3, pot, cls);
}

// round 8
// speedup vs baseline: 1.4312x; 1.4312x over previous
#include <cuda_runtime.h>
#include <stdint.h>

#define NB 32
#define NT 15

// ---------------- device scratch (no cudaMalloc allowed) ----------------
static __device__ __align__(16) int8_t  g_tf0 [NB*18*32*32];   // 0 iff fires at t=0, else 15
static __device__ __align__(16) float   g_w1q [3*882*32];      // w1: [fg][k][32 lanes]
static __device__ __align__(16) int8_t  g_ft1p[NB*90*15*16];   // pooled L1, row-stride 16
static __device__              uint8_t g_cflag1[NB*90];
static __device__              int     g_any1[NB];
static __device__ __align__(16) int8_t  g_ft2p[NB*250*16];     // pooled L2 fire times
static __device__              uint8_t g_cflag2[NB*250];
static __device__              int     g_any2[NB];
static __device__              float   g_wsat2[250*36];        // SAT of channel-summed w2
static __device__              float   g_wsat3[200*36];        // SAT of channel-summed w3

// ===========================================================================
// k_prep: weight SATs, w1 repack, t0-plane marker, flag zeroing.
// Blocks: [0,450) wsat | [450,781) wrep | [781,1357) t0 marker | 1357 zero.
__global__ __launch_bounds__(256) void k_prep(const float* __restrict__ inp,
                                              const float* __restrict__ w1,
                                              const float* __restrict__ w2,
                                              const float* __restrict__ w3) {
    int bid = blockIdx.x, tid = threadIdx.x;
    if (bid < 450) {
        __shared__ float s_part[250];
        __shared__ float s25[25];
        const float* src; int C; float* dst; int f;
        if (bid < 250) { f = bid;     src = w2; C = 90;  dst = g_wsat2 + f*36; }
        else           { f = bid-250; src = w3; C = 250; dst = g_wsat3 + f*36; }
        if (tid < 250) {
            int p = tid / 10, g = tid % 10;
            float s = 0.0f;
            for (int c = g; c < C; c += 10) s += src[((size_t)f*C + c)*25 + p];
            s_part[p*10 + g] = s;
        }
        __syncthreads();
        if (tid < 25) {
            float s = 0.0f;
            for (int g = 0; g < 10; g++) s += s_part[tid*10 + g];
            s25[tid] = s;
        }
        __syncthreads();
        if (tid < 36) {
            int i = tid / 6, j = tid % 6;
            float s = 0.0f;
            for (int ii = 0; ii < i; ii++)
                for (int jj = 0; jj < j; jj++) s += s25[ii*5 + jj];
            dst[tid] = s;
        }
    } else if (bid < 781) {
        int idx = (bid - 450)*256 + tid;
        if (idx < 3*882*32) {
            int lane = idx & 31, k = (idx >> 5) % 882, fg = idx / (882*32);
            int f = fg*32 + lane;
            g_w1q[idx] = (f < 90) ? w1[f*882 + k] : 0.0f;
        }
    } else if (bid < 1357) {
        // t=0 plane marker only: tf==0 <=> inp[b,0,chw] == 1 (cumulative wave)
        int idx4 = (bid - 781)*256 + tid;           // exactly 32*18*1024/4
        int base = idx4 * 4;
        int b    = base / (18*1024);
        int chw  = base - b*(18*1024);
        float4 v = *(const float4*)(inp + (size_t)b*(NT*18*1024) + chw);
        uchar4 o;
        o.x = (v.x > 0.5f) ? 0 : 15;
        o.y = (v.y > 0.5f) ? 0 : 15;
        o.z = (v.z > 0.5f) ? 0 : 15;
        o.w = (v.w > 0.5f) ? 0 : 15;
        *(uchar4*)(g_tf0 + base) = o;
    } else {
        for (int i = tid; i < NB*90;  i += 256) g_cflag1[i] = 0;
        for (int i = tid; i < NB*250; i += 256) g_cflag2[i] = 0;
        if (tid < NB) { g_any1[tid] = 0; g_any2[tid] = 0; }
    }
}

// ===========================================================================
// conv1 slow path (essentially never taken): per-t rescan straight from input.
__device__ __noinline__ int conv1_slow(const float* __restrict__ inp,
                                       int b, int f, int y, int x,
                                       const float* __restrict__ w1) {
    const float* wf = w1 + (size_t)f*882;
    for (int t = 1; t < 15; t++) {
        const float* pl = inp + ((size_t)(b*NT + t))*18*1024;
        float cum = 0.0f;
        for (int c = 0; c < 18; c++)
            for (int i = 0; i < 7; i++) {
                int h = y + i - 2;
                if ((unsigned)h >= 32u) continue;
                for (int j = 0; j < 7; j++) {
                    int w = x + j - 2;
                    if ((unsigned)w >= 32u) continue;
                    if (pl[(c << 10) + (h << 5) + w] > 0.5f) cum += wf[c*49 + i*7 + j];
                }
            }
        if (cum > 15.0f) return t;
    }
    return 15;
}

// ===========================================================================
// conv1 (round-3 proven): lane=filter (32/warp), warp = 4 adjacent output
// pixels, 1 row per warp. Warp-uniform bitmask iteration over tf==0 taps.
// Fused 2x2 pool + channel flags. grid (8 row-quads, 3 fgroups, NB).
#define CONV1_SMEM (882*32*4 + 180*8 + 4096)
extern __shared__ unsigned char smem_raw[];
__global__ __launch_bounds__(1024, 1) void k_conv1(const float* __restrict__ inp,
                                                   const float* __restrict__ w1) {
    float*    s_w  = (float*)smem_raw;
    uint64_t* s_m  = (uint64_t*)(smem_raw + 882*32*4);
    int8_t*   s_ft = (int8_t*)(smem_raw + 882*32*4 + 180*8);
    int tid = threadIdx.x;
    int rq = blockIdx.x, fg = blockIdx.y, b = blockIdx.z;
    int lane = tid & 31, w = tid >> 5;

    const uint4* wsrc = (const uint4*)(g_w1q + (size_t)fg*882*32);
    uint4* wdst = (uint4*)s_w;
    for (int i = tid; i < 882*32/4; i += 1024) wdst[i] = wsrc[i];
    // row bitmasks: bit (w_in+2) set iff tf==0
    if (tid < 180) {
        int c = tid / 10, rr = tid % 10;
        int h = rq*4 + rr - 2;
        uint64_t mask = 0;
        if ((unsigned)h < 32u) {
            const uint32_t* row = (const uint32_t*)(g_tf0 + ((b*18 + c) << 10) + (h << 5));
            uint32_t bits = 0;
#pragma unroll
            for (int k2 = 0; k2 < 8; k2++) {
                uint32_t nib = ((__vseteq4(row[k2], 0u) * 0x01020408u) >> 24) & 0xFu;
                bits |= nib << (k2*4);
            }
            mask = ((uint64_t)bits) << 2;
        }
        s_m[c*10 + rr] = mask;
    }
    __syncthreads();

    int dy = w >> 3, q = w & 7;
    int y = rq*4 + dy, x0 = q*4;
    float a0 = 0.f, a1 = 0.f, a2 = 0.f, a3 = 0.f;
    if (y < 30) {
        for (int c = 0; c < 18; c++) {
            const uint64_t* mrow = s_m + c*10 + dy;
            const float* wc = s_w + c*49*32 + lane;
#pragma unroll
            for (int i = 0; i < 7; i++) {
                uint32_t wnd = (uint32_t)(mrow[i] >> x0) & 0x3FFu;  // bits p: j=p-k
                const float* wi = wc + i*7*32;
                while (wnd) {
                    int p = __ffs(wnd) - 1;
                    wnd &= wnd - 1;
                    if (p <= 6)           a0 += wi[p*32];
                    if (p >= 1 && p <= 7) a1 += wi[(p-1)*32];
                    if (p >= 2 && p <= 8) a2 += wi[(p-2)*32];
                    if (p >= 3)           a3 += wi[(p-3)*32];
                }
            }
        }
    }
    int f = fg*32 + lane;
    float aa[4] = {a0, a1, a2, a3};
#pragma unroll
    for (int k = 0; k < 4; k++) {
        int x = x0 + k;
        int ft = 0;
        if (y < 30 && x < 30 && f < 90)
            ft = (aa[k] > 15.0f) ? 0 : conv1_slow(inp, b, f, y, x, w1);
        s_ft[(dy*32 + x)*32 + lane] = (int8_t)ft;
    }
    __syncthreads();

    // fused 2x2 min-pool + channel flags
    bool nz = false;
    if (tid < 960) {
        int pf = tid & 31;
        int rest = tid >> 5;            // 0..29
        int pcol = rest % 15;
        int pr   = rest / 15;           // 0..1
        int prow = rq*2 + pr;
        int r0 = pr*2, c0 = pcol*2;
        int v0 = s_ft[(r0*32     + c0  )*32 + pf];
        int v1 = s_ft[(r0*32     + c0+1)*32 + pf];
        int v2 = s_ft[((r0+1)*32 + c0  )*32 + pf];
        int v3 = s_ft[((r0+1)*32 + c0+1)*32 + pf];
        int m0 = v0 < v1 ? v0 : v1;
        int m1 = v2 < v3 ? v2 : v3;
        int pv = m0 < m1 ? m0 : m1;
        int ff = fg*32 + pf;
        if (prow < 15 && ff < 90) {
            g_ft1p[((b*90 + ff)*15 + prow)*16 + pcol] = (int8_t)pv;
            if (pv) { g_cflag1[b*90 + ff] = 1; nz = true; }
        }
    }
    int cnt = __syncthreads_count(nz);
    if (tid == 0 && cnt) atomicAdd(&g_any1[b], 1);
}

// ===========================================================================
// conv2 (round-3 proven): SAT fast path + per-channel corrections.
// Fused 3x3 pool + layer-2 flags.
__global__ __launch_bounds__(192) void k_conv2(const float* __restrict__ w2) {
    __shared__ __align__(16) int8_t s_tf[90*240];
    __shared__ float   s_sat[36];
    __shared__ float   s_h[14*192];
    __shared__ uint8_t s_flags[90];
    __shared__ int8_t  s_ftp[169];
    int tid = threadIdx.x;
    int f = blockIdx.x, b = blockIdx.y;
    int any = g_any1[b];

    if (tid < 36) s_sat[tid] = g_wsat2[f*36 + tid];
    if (any) {
        const uint4* src = (const uint4*)(g_ft1p + (size_t)b*90*240);
        uint4* dst = (uint4*)s_tf;
        for (int i = tid; i < 90*240/16; i += 192) dst[i] = src[i];
        if (tid < 90) s_flags[tid] = g_cflag1[b*90 + tid];
        for (int t = 0; t < 14; t++) s_h[t*192 + tid] = 0.0f;
    }
    __syncthreads();

    if (tid < 169) {
        int y = tid / 13, x = tid - y*13;
        int r0 = max(0, y-1), r1 = min(14, y+3);
        int c0 = max(0, x-1), c1 = min(14, x+3);
        int i0 = r0 - (y-1), i1 = r1 - (y-1);
        int j0 = c0 - (x-1), j1 = c1 - (x-1);
        float a0 = s_sat[(i1+1)*6 + (j1+1)] - s_sat[i0*6 + (j1+1)]
                 - s_sat[(i1+1)*6 + j0]     + s_sat[i0*6 + j0];
        int ft;
        if (!any) {
            ft = (a0 > 10.0f) ? 0 : 15;
        } else {
            float* hb = s_h + tid;
            for (int c = 0; c < 90; c++) {
                if (!s_flags[c]) continue;
                const int8_t* tp = s_tf + c*240;
                const float*  wp = w2 + ((size_t)f*90 + c)*25;
                for (int r = r0; r <= r1; r++)
                    for (int cc = c0; cc <= c1; cc++) {
                        int tf = tp[r*16 + cc];
                        if (tf) {
                            float wv = __ldg(wp + (r-(y-1))*5 + (cc-(x-1)));
                            a0 -= wv;
                            if (tf < 15) hb[(tf-1)*192] += wv;
                        }
                    }
            }
            float cum = a0; ft = 15;
            if (cum > 10.0f) ft = 0;
#pragma unroll
            for (int t = 1; t < 15; t++) {
                cum += hb[(t-1)*192];
                if (ft == 15 && cum > 10.0f) ft = t;
            }
        }
        s_ftp[tid] = (int8_t)ft;
    }
    __syncthreads();

    bool nz = false;
    if (tid < 16) {
        int yy = tid >> 2, xx = tid & 3;
        const int8_t* bp = s_ftp + yy*39 + xx*3;
        int v = 15;
#pragma unroll
        for (int dy = 0; dy < 3; dy++)
#pragma unroll
            for (int dx = 0; dx < 3; dx++) {
                int u = bp[dy*13 + dx];
                v = u < v ? u : v;
            }
        g_ft2p[(b*250 + f)*16 + tid] = (int8_t)v;
        nz = (v != 0);
    }
    int cnt = __syncthreads_count(nz);
    if (tid == 0 && cnt) { g_cflag2[b*250 + f] = 1; atomicAdd(&g_any2[b], 1); }
}

// ===========================================================================
// conv3 (round-3 proven): SAT fast path, corrections + histogram otherwise.
__global__ __launch_bounds__(256) void k_conv3(const float* __restrict__ w3,
                                               float* __restrict__ pot) {
    __shared__ __align__(16) int8_t s_tf[250*16];
    __shared__ float   s_sat[16*36];
    __shared__ float   s_h[14*256];
    __shared__ uint8_t s_flags[250];
    int tid = threadIdx.x;
    int fg = blockIdx.x, b = blockIdx.y;
    int any = g_any2[b];

    for (int i = tid; i < 16*36; i += 256) {
        int f = fg*16 + i/36;
        s_sat[i] = (f < 200) ? g_wsat3[f*36 + i%36] : 0.0f;
    }
    if (any) {
        const uint4* src = (const uint4*)(g_ft2p + (size_t)b*250*16);
        for (int i = tid; i < 250; i += 256) ((uint4*)s_tf)[i] = src[i];
        if (tid < 250) s_flags[tid] = g_cflag2[b*250 + tid];
        for (int t = 0; t < 14; t++) s_h[t*256 + tid] = 0.0f;
    }
    __syncthreads();

    int fi = tid >> 4, p = tid & 15;
    int f = fg*16 + fi;
    if (f < 200) {
        int y = p >> 2, x = p & 3;
        int r0 = max(0, y-2), r1 = min(3, y+2);
        int c0 = max(0, x-2), c1 = min(3, x+2);
        int i0 = r0 - (y-2), i1 = r1 - (y-2);
        int j0 = c0 - (x-2), j1 = c1 - (x-2);
        const float* S = s_sat + fi*36;
        float a0 = S[(i1+1)*6 + (j1+1)] - S[i0*6 + (j1+1)]
                 - S[(i1+1)*6 + j0]     + S[i0*6 + j0];
        float* o = pot + ((size_t)b*NT*200 + f)*16 + p;
        if (!any) {
#pragma unroll
            for (int t = 0; t < NT; t++) o[(size_t)t * 3200] = a0;
        } else {
            float* hb = s_h + tid;
            for (int c = 0; c < 250; c++) {
                if (!s_flags[c]) continue;
                const int8_t* tp = s_tf + c*16;
                const float*  wp = w3 + ((size_t)f*250 + c)*25;
                for (int r = r0; r <= r1; r++)
                    for (int cc = c0; cc <= c1; cc++) {
                        int tf = tp[r*4 + cc];
                        if (tf) {
                            float wv = __ldg(wp + (r-(y-2))*5 + (cc-(x-2)));
                            a0 -= wv;
                            if (tf < 15) hb[(tf-1)*256] += wv;
                        }
                    }
            }
            float cum = a0;
#pragma unroll
            for (int t = 0; t < NT; t++) {
                if (t) cum += hb[(t-1)*256];
                o[(size_t)t * 3200] = cum;
            }
        }
    }
}

// ===========================================================================
// winner (round-3 proven): argmax over pot3[:,14] > 0, earliest index on ties.
__global__ void k_winner(const float* __restrict__ pot, float* __restrict__ cls) {
    __shared__ float s_v[256];
    __shared__ int   s_i[256];
    int b = blockIdx.x, tid = threadIdx.x;
    const float* p = pot + ((size_t)b*NT + 14) * 3200;
    float bv = 0.0f; int bi = 1 << 30;
    for (int i = tid; i < 3200; i += 256) {
        float v = p[i];
        if (v > bv) { bv = v; bi = i; }
    }
    s_v[tid] = bv; s_i[tid] = bi;
    __syncthreads();
    for (int s = 128; s > 0; s >>= 1) {
        if (tid < s) {
            float ov = s_v[tid+s]; int oi = s_i[tid+s];
            if (ov > s_v[tid] || (ov == s_v[tid] && oi < s_i[tid])) {
                s_v[tid] = ov; s_i[tid] = oi;
            }
        }
        __syncthreads();
    }
    if (tid == 0)
        cls[b] = (s_v[0] > 0.0f) ? (float)((s_i[0] >> 4) / 20) : -1.0f;
}

// ===========================================================================
extern "C" void kernel_launch(void* const* d_in, const int* in_sizes, int n_in,
                              void* d_out, int out_size) {
    const float* inp = (const float*)d_in[0];
    const float* w1  = (const float*)d_in[1];
    const float* w2  = (const float*)d_in[2];
    const float* w3  = (const float*)d_in[3];

    float* out = (float*)d_out;
    float* pot = out;
    float* cls = nullptr;
    if (out_size == NB + NB*NT*3200) {   // (cls, pot3) concatenated
        cls = out;
        pot = out + NB;
    }

    static bool attr_set = false;
    if (!attr_set) {
        cudaFuncSetAttribute(k_conv1, cudaFuncAttributeMaxDynamicSharedMemorySize,
                             CONV1_SMEM);
        attr_set = true;
    }

    k_prep <<<1358, 256>>>(inp, w1, w2, w3);
    k_conv1<<<dim3(8, 3, NB), 1024, CONV1_SMEM>>>(inp, w1);
    k_conv2<<<dim3(250, NB), 192>>>(w2);
    k_conv3<<<dim3(13, NB), 256>>>(w3, pot);
    if (cls) k_winner<<<NB, 256>>>(pot, cls);
}

// round 9
// speedup vs baseline: 2.3536x; 1.6445x over previous
#include <cuda_runtime.h>
#include <stdint.h>

#define NB 32
#define NT 15

// ---------------- device scratch (no cudaMalloc allowed) ----------------
static __device__ __align__(16) int8_t  g_ft1p[NB*90*15*16];   // pooled L1, row-stride 16 (zeroed by prep)
static __device__              uint8_t g_cflag1[NB*90];
static __device__              int     g_any1[NB];
static __device__ __align__(16) int8_t  g_ft2p[NB*250*16];     // pooled L2 fire times
static __device__              uint8_t g_cflag2[NB*250];
static __device__              int     g_any2[NB];
static __device__              float   g_wsat2[250*36];        // SAT of channel-summed w2
static __device__              float   g_wsat3[200*36];        // SAT of channel-summed w3
static __device__              int8_t  g_excft[(size_t)NB*900*90]; // exact ft for exceptional pixels
static __device__              unsigned g_wmink = 0xFFFFFFFFu; // ordered-int key of min(w1) (atomicMin, idempotent)

// float <-> ascending-ordered uint key
__device__ __forceinline__ unsigned f2key(float v) {
    unsigned b = __float_as_uint(v);
    return (b & 0x80000000u) ? ~b : (b | 0x80000000u);
}
__device__ __forceinline__ float key2f(unsigned k) {
    return (k & 0x80000000u) ? __uint_as_float(k ^ 0x80000000u)
                             : __uint_as_float(~k);
}

// ===========================================================================
// k_prep: weight SATs | w1-min reduction | ft1p zero | flag zero.
// Blocks: [0,450) wsat | [450,761) wmin | [761,930) ft1p zero | 930 flags.
__global__ __launch_bounds__(256) void k_prep(const float* __restrict__ w1,
                                              const float* __restrict__ w2,
                                              const float* __restrict__ w3) {
    int bid = blockIdx.x, tid = threadIdx.x;
    if (bid < 450) {
        __shared__ float s_part[250];
        __shared__ float s25[25];
        const float* src; int C; float* dst; int f;
        if (bid < 250) { f = bid;     src = w2; C = 90;  dst = g_wsat2 + f*36; }
        else           { f = bid-250; src = w3; C = 250; dst = g_wsat3 + f*36; }
        if (tid < 250) {
            int p = tid / 10, g = tid % 10;
            float s = 0.0f;
            for (int c = g; c < C; c += 10) s += src[((size_t)f*C + c)*25 + p];
            s_part[p*10 + g] = s;
        }
        __syncthreads();
        if (tid < 25) {
            float s = 0.0f;
            for (int g = 0; g < 10; g++) s += s_part[tid*10 + g];
            s25[tid] = s;
        }
        __syncthreads();
        if (tid < 36) {
            int i = tid / 6, j = tid % 6;
            float s = 0.0f;
            for (int ii = 0; ii < i; ii++)
                for (int jj = 0; jj < j; jj++) s += s25[ii*5 + jj];
            dst[tid] = s;
        }
    } else if (bid < 761) {
        __shared__ unsigned s_k[256];
        int idx = (bid - 450)*256 + tid;
        unsigned k = 0xFFFFFFFFu;
        if (idx < 90*882) k = f2key(w1[idx]);
        s_k[tid] = k;
        __syncthreads();
        for (int s = 128; s > 0; s >>= 1) {
            if (tid < s) { unsigned o = s_k[tid+s]; if (o < s_k[tid]) s_k[tid] = o; }
            __syncthreads();
        }
        if (tid == 0) atomicMin(&g_wmink, s_k[0]);
    } else if (bid < 930) {
        int i = (bid - 761)*256 + tid;
        if (i < NB*90*15*16/16) ((uint4*)g_ft1p)[i] = make_uint4(0,0,0,0);
    } else {
        for (int i = tid; i < NB*90;  i += 256) g_cflag1[i] = 0;
        for (int i = tid; i < NB*250; i += 256) g_cflag2[i] = 0;
        if (tid < NB) { g_any1[tid] = 0; g_any2[tid] = 0; }
    }
}

// ===========================================================================
// conv1 slow path (rare): per-t rescan straight from input. Exact fp32.
__device__ __noinline__ int conv1_slow(const float* __restrict__ inp,
                                       int b, int f, int y, int x,
                                       const float* __restrict__ w1) {
    const float* wf = w1 + (size_t)f*882;
    for (int t = 1; t < 15; t++) {
        const float* pl = inp + ((size_t)(b*NT + t))*18*1024;
        float cum = 0.0f;
        for (int c = 0; c < 18; c++)
            for (int i = 0; i < 7; i++) {
                int h = y + i - 2;
                if ((unsigned)h >= 32u) continue;
                for (int j = 0; j < 7; j++) {
                    int w = x + j - 2;
                    if ((unsigned)w >= 32u) continue;
                    if (pl[(c << 10) + (h << 5) + w] > 0.5f) cum += wf[c*49 + i*7 + j];
                }
            }
        if (cum > 15.0f) return t;
    }
    return 15;
}

// ===========================================================================
// conv1: one block per batch, thread = output pixel. ntaps popcount + wmin
// bound proves ft==0 for ALL 90 filters at ~all pixels; exceptional pixels
// get exact per-filter fp32 treatment. Pooled output nonzero only when all
// four pool-mates are exceptional (resolved from g_excft).
__global__ __launch_bounds__(1024) void k_conv1(const float* __restrict__ inp,
                                                const float* __restrict__ w1) {
    __shared__ uint64_t s_m[18*34];      // padded row masks (bit w+2 = fires at t=0)
    __shared__ uint16_t s_nt[960];       // ntaps per pixel (tid = y*32+x)
    __shared__ uint16_t s_elist[960];
    __shared__ int      s_ne;
    int b = blockIdx.x, tid = threadIdx.x;
    float wmin = key2f(g_wmink);
    if (tid == 0) s_ne = 0;

    if (tid < 612) {
        int c = tid / 34, hh = tid % 34, h = hh - 2;
        uint64_t mask = 0;
        if ((unsigned)h < 32u) {
            const float4* row = (const float4*)(inp + ((size_t)b*NT*18 + c)*1024 + (h << 5));
            uint32_t bits = 0;
#pragma unroll
            for (int k = 0; k < 8; k++) {
                float4 v = row[k];
                bits |= (v.x > 0.5f ? 1u : 0u) << (k*4);
                bits |= (v.y > 0.5f ? 2u : 0u) << (k*4);
                bits |= (v.z > 0.5f ? 4u : 0u) << (k*4);
                bits |= (v.w > 0.5f ? 8u : 0u) << (k*4);
            }
            mask = ((uint64_t)bits) << 2;
        }
        s_m[tid] = mask;
    }
    if (tid < 960) s_nt[tid] = 0;
    __syncthreads();

    int y = tid >> 5, x = tid & 31;
    if (y < 30 && x < 30) {
        int nt = 0;
        for (int c = 0; c < 18; c++) {
            const uint64_t* base = s_m + c*34 + y;
#pragma unroll
            for (int i = 0; i < 7; i++)
                nt += __popc((uint32_t)(base[i] >> x) & 0x7Fu);
        }
        s_nt[tid] = (uint16_t)nt;
        if (!((float)nt * wmin > 15.0f)) {     // cannot prove fires-at-0 => exact path
            int sl = atomicAdd(&s_ne, 1);
            s_elist[sl] = (uint16_t)tid;
        }
    }
    __syncthreads();

    int ne = s_ne;
    // exact per-filter processing of exceptional pixels, 11 pixels x 90 filters per wave
    for (int base = 0; base < ne; base += 11) {
        int slot = tid / 90, f = tid - slot*90;
        if (slot < 11 && base + slot < ne) {
            int pix = s_elist[base + slot];
            int yy = pix >> 5, xx = pix & 31;
            float pot0 = 0.0f;
            const float* wf = w1 + (size_t)f*882;
            for (int c = 0; c < 18; c++) {
                const uint64_t* mb = s_m + c*34 + yy;
#pragma unroll
                for (int i = 0; i < 7; i++) {
                    uint32_t wnd = (uint32_t)(mb[i] >> xx) & 0x7Fu;
                    const float* wr = wf + c*49 + i*7;
                    while (wnd) {
                        int p = __ffs(wnd) - 1;
                        wnd &= wnd - 1;
                        pot0 += __ldg(wr + p);
                    }
                }
            }
            int ft = (pot0 > 15.0f) ? 0 : conv1_slow(inp, b, f, yy, xx, w1);
            g_excft[((size_t)b*900 + yy*30 + xx)*90 + f] = (int8_t)ft;
        }
        __syncthreads();
    }

    // pooled resolution: nonzero pooled value requires all 4 mates exceptional
    bool nz = false;
    if (ne > 0 && tid < 225) {
        int py = tid / 15, px = tid % 15;
        int m00 = (py*2)*32 + px*2;
        int m01 = m00 + 1, m10 = m00 + 32, m11 = m10 + 1;
        bool e00 = !((float)s_nt[m00]*wmin > 15.0f);
        bool e01 = !((float)s_nt[m01]*wmin > 15.0f);
        bool e10 = !((float)s_nt[m10]*wmin > 15.0f);
        bool e11 = !((float)s_nt[m11]*wmin > 15.0f);
        if (e00 && e01 && e10 && e11) {
            int yy = py*2, xx = px*2;
            const int8_t* q00 = g_excft + ((size_t)b*900 + yy*30     + xx    )*90;
            const int8_t* q01 = g_excft + ((size_t)b*900 + yy*30     + xx + 1)*90;
            const int8_t* q10 = g_excft + ((size_t)b*900 + (yy+1)*30 + xx    )*90;
            const int8_t* q11 = g_excft + ((size_t)b*900 + (yy+1)*30 + xx + 1)*90;
            for (int f = 0; f < 90; f++) {
                int v0 = q00[f], v1 = q01[f], v2 = q10[f], v3 = q11[f];
                int m0 = v0 < v1 ? v0 : v1;
                int m1 = v2 < v3 ? v2 : v3;
                int pv = m0 < m1 ? m0 : m1;
                if (pv) {
                    g_ft1p[((b*90 + f)*15 + py)*16 + px] = (int8_t)pv;
                    g_cflag1[b*90 + f] = 1;
                    nz = true;
                }
            }
        }
    }
    int cnt = __syncthreads_count(nz);
    if (tid == 0 && cnt) atomicAdd(&g_any1[b], 1);
}

// ===========================================================================
// conv2 (proven): SAT fast path + per-channel corrections.
// Fused 3x3 pool + layer-2 flags.
__global__ __launch_bounds__(192) void k_conv2(const float* __restrict__ w2) {
    __shared__ __align__(16) int8_t s_tf[90*240];
    __shared__ float   s_sat[36];
    __shared__ float   s_h[14*192];
    __shared__ uint8_t s_flags[90];
    __shared__ int8_t  s_ftp[169];
    int tid = threadIdx.x;
    int f = blockIdx.x, b = blockIdx.y;
    int any = g_any1[b];

    if (tid < 36) s_sat[tid] = g_wsat2[f*36 + tid];
    if (any) {
        const uint4* src = (const uint4*)(g_ft1p + (size_t)b*90*240);
        uint4* dst = (uint4*)s_tf;
        for (int i = tid; i < 90*240/16; i += 192) dst[i] = src[i];
        if (tid < 90) s_flags[tid] = g_cflag1[b*90 + tid];
        for (int t = 0; t < 14; t++) s_h[t*192 + tid] = 0.0f;
    }
    __syncthreads();

    if (tid < 169) {
        int y = tid / 13, x = tid - y*13;
        int r0 = max(0, y-1), r1 = min(14, y+3);
        int c0 = max(0, x-1), c1 = min(14, x+3);
        int i0 = r0 - (y-1), i1 = r1 - (y-1);
        int j0 = c0 - (x-1), j1 = c1 - (x-1);
        float a0 = s_sat[(i1+1)*6 + (j1+1)] - s_sat[i0*6 + (j1+1)]
                 - s_sat[(i1+1)*6 + j0]     + s_sat[i0*6 + j0];
        int ft;
        if (!any) {
            ft = (a0 > 10.0f) ? 0 : 15;
        } else {
            float* hb = s_h + tid;
            for (int c = 0; c < 90; c++) {
                if (!s_flags[c]) continue;
                const int8_t* tp = s_tf + c*240;
                const float*  wp = w2 + ((size_t)f*90 + c)*25;
                for (int r = r0; r <= r1; r++)
                    for (int cc = c0; cc <= c1; cc++) {
                        int tf = tp[r*16 + cc];
                        if (tf) {
                            float wv = __ldg(wp + (r-(y-1))*5 + (cc-(x-1)));
                            a0 -= wv;
                            if (tf < 15) hb[(tf-1)*192] += wv;
                        }
                    }
            }
            float cum = a0; ft = 15;
            if (cum > 10.0f) ft = 0;
#pragma unroll
            for (int t = 1; t < 15; t++) {
                cum += hb[(t-1)*192];
                if (ft == 15 && cum > 10.0f) ft = t;
            }
        }
        s_ftp[tid] = (int8_t)ft;
    }
    __syncthreads();

    bool nz = false;
    if (tid < 16) {
        int yy = tid >> 2, xx = tid & 3;
        const int8_t* bp = s_ftp + yy*39 + xx*3;
        int v = 15;
#pragma unroll
        for (int dy = 0; dy < 3; dy++)
#pragma unroll
            for (int dx = 0; dx < 3; dx++) {
                int u = bp[dy*13 + dx];
                v = u < v ? u : v;
            }
        g_ft2p[(b*250 + f)*16 + tid] = (int8_t)v;
        nz = (v != 0);
    }
    int cnt = __syncthreads_count(nz);
    if (tid == 0 && cnt) { g_cflag2[b*250 + f] = 1; atomicAdd(&g_any2[b], 1); }
}

// ===========================================================================
// conv3 (proven): SAT fast path, corrections + histogram otherwise.
__global__ __launch_bounds__(256) void k_conv3(const float* __restrict__ w3,
                                               float* __restrict__ pot) {
    __shared__ __align__(16) int8_t s_tf[250*16];
    __shared__ float   s_sat[16*36];
    __shared__ float   s_h[14*256];
    __shared__ uint8_t s_flags[250];
    int tid = threadIdx.x;
    int fg = blockIdx.x, b = blockIdx.y;
    int any = g_any2[b];

    for (int i = tid; i < 16*36; i += 256) {
        int f = fg*16 + i/36;
        s_sat[i] = (f < 200) ? g_wsat3[f*36 + i%36] : 0.0f;
    }
    if (any) {
        const uint4* src = (const uint4*)(g_ft2p + (size_t)b*250*16);
        for (int i = tid; i < 250; i += 256) ((uint4*)s_tf)[i] = src[i];
        if (tid < 250) s_flags[tid] = g_cflag2[b*250 + tid];
        for (int t = 0; t < 14; t++) s_h[t*256 + tid] = 0.0f;
    }
    __syncthreads();

    int fi = tid >> 4, p = tid & 15;
    int f = fg*16 + fi;
    if (f < 200) {
        int y = p >> 2, x = p & 3;
        int r0 = max(0, y-2), r1 = min(3, y+2);
        int c0 = max(0, x-2), c1 = min(3, x+2);
        int i0 = r0 - (y-2), i1 = r1 - (y-2);
        int j0 = c0 - (x-2), j1 = c1 - (x-2);
        const float* S = s_sat + fi*36;
        float a0 = S[(i1+1)*6 + (j1+1)] - S[i0*6 + (j1+1)]
                 - S[(i1+1)*6 + j0]     + S[i0*6 + j0];
        float* o = pot + ((size_t)b*NT*200 + f)*16 + p;
        if (!any) {
#pragma unroll
            for (int t = 0; t < NT; t++) o[(size_t)t * 3200] = a0;
        } else {
            float* hb = s_h + tid;
            for (int c = 0; c < 250; c++) {
                if (!s_flags[c]) continue;
                const int8_t* tp = s_tf + c*16;
                const float*  wp = w3 + ((size_t)f*250 + c)*25;
                for (int r = r0; r <= r1; r++)
                    for (int cc = c0; cc <= c1; cc++) {
                        int tf = tp[r*4 + cc];
                        if (tf) {
                            float wv = __ldg(wp + (r-(y-2))*5 + (cc-(x-2)));
                            a0 -= wv;
                            if (tf < 15) hb[(tf-1)*256] += wv;
                        }
                    }
            }
            float cum = a0;
#pragma unroll
            for (int t = 0; t < NT; t++) {
                if (t) cum += hb[(t-1)*256];
                o[(size_t)t * 3200] = cum;
            }
        }
    }
}

// ===========================================================================
// winner (proven): argmax over pot3[:,14] > 0, earliest index on ties.
__global__ void k_winner(const float* __restrict__ pot, float* __restrict__ cls) {
    __shared__ float s_v[256];
    __shared__ int   s_i[256];
    int b = blockIdx.x, tid = threadIdx.x;
    const float* p = pot + ((size_t)b*NT + 14) * 3200;
    float bv = 0.0f; int bi = 1 << 30;
    for (int i = tid; i < 3200; i += 256) {
        float v = p[i];
        if (v > bv) { bv = v; bi = i; }
    }
    s_v[tid] = bv; s_i[tid] = bi;
    __syncthreads();
    for (int s = 128; s > 0; s >>= 1) {
        if (tid < s) {
            float ov = s_v[tid+s]; int oi = s_i[tid+s];
            if (ov > s_v[tid] || (ov == s_v[tid] && oi < s_i[tid])) {
                s_v[tid] = ov; s_i[tid] = oi;
            }
        }
        __syncthreads();
    }
    if (tid == 0)
        cls[b] = (s_v[0] > 0.0f) ? (float)((s_i[0] >> 4) / 20) : -1.0f;
}

// ===========================================================================
extern "C" void kernel_launch(void* const* d_in, const int* in_sizes, int n_in,
                              void* d_out, int out_size) {
    const float* inp = (const float*)d_in[0];
    const float* w1  = (const float*)d_in[1];
    const float* w2  = (const float*)d_in[2];
    const float* w3  = (const float*)d_in[3];

    float* out = (float*)d_out;
    float* pot = out;
    float* cls = nullptr;
    if (out_size == NB + NB*NT*3200) {   // (cls, pot3) concatenated
        cls = out;
        pot = out + NB;
    }

    k_prep  <<<931, 256>>>(w1, w2, w3);
    k_conv1 <<<NB, 1024>>>(inp, w1);
    k_conv2 <<<dim3(250, NB), 192>>>(w2);
    k_conv3 <<<dim3(13, NB), 256>>>(w3, pot);
    if (cls) k_winner<<<NB, 256>>>(pot, cls);
}

// round 10
// speedup vs baseline: 2.3658x; 1.0052x over previous
#include <cuda_runtime.h>
#include <stdint.h>

#define NB 32
#define NT 15

// ---------------- device scratch (no cudaMalloc allowed) ----------------
static __device__ __align__(16) int8_t  g_ft1p[NB*90*15*16];   // pooled L1, row-stride 16 (zeroed by prep)
static __device__              uint8_t g_cflag1[NB*90];
static __device__              int     g_any1[NB];
static __device__ __align__(16) int8_t  g_ft2p[NB*250*16];     // pooled L2 fire times
static __device__              uint8_t g_cflag2[NB*250];
static __device__              int     g_any2[NB];
static __device__              float   g_wsat2[250*36];        // SAT of channel-summed w2
static __device__              float   g_wsat3[200*36];        // SAT of channel-summed w3
static __device__              int8_t  g_excft[(size_t)NB*900*90]; // exact ft for exceptional pixels
static __device__              unsigned g_wmink = 0xFFFFFFFFu; // ordered-int key of min(w1)

// float <-> ascending-ordered uint key
__device__ __forceinline__ unsigned f2key(float v) {
    unsigned b = __float_as_uint(v);
    return (b & 0x80000000u) ? ~b : (b | 0x80000000u);
}
__device__ __forceinline__ float key2f(unsigned k) {
    return (k & 0x80000000u) ? __uint_as_float(k ^ 0x80000000u)
                             : __uint_as_float(~k);
}

// ===========================================================================
// k_prep: weight SATs (coalesced smem-staged) | w1-min | ft1p zero | flags.
// Blocks: [0,450) wsat | [450,761) wmin | [761,930) ft1p zero | 930 flags.
__global__ __launch_bounds__(256) void k_prep(const float* __restrict__ w1,
                                              const float* __restrict__ w2,
                                              const float* __restrict__ w3) {
    int bid = blockIdx.x, tid = threadIdx.x;
    if (bid < 450) {
        __shared__ float s_w[6250];        // staged filter block (C*25, max 250*25)
        __shared__ float s_part[250];
        __shared__ float s25[25];
        const float* src; int C; float* dst; int f;
        if (bid < 250) { f = bid;     src = w2; C = 90;  dst = g_wsat2 + f*36; }
        else           { f = bid-250; src = w3; C = 250; dst = g_wsat3 + f*36; }
        // coalesced stage of this filter's C*25 weights
        const float* fsrc = src + (size_t)f*C*25;
        for (int i = tid; i < C*25; i += 256) s_w[i] = fsrc[i];
        __syncthreads();
        // identical reduction order as before, but from smem
        if (tid < 250) {
            int p = tid / 10, g = tid % 10;
            float s = 0.0f;
            for (int c = g; c < C; c += 10) s += s_w[c*25 + p];
            s_part[p*10 + g] = s;
        }
        __syncthreads();
        if (tid < 25) {
            float s = 0.0f;
            for (int g = 0; g < 10; g++) s += s_part[tid*10 + g];
            s25[tid] = s;
        }
        __syncthreads();
        if (tid < 36) {
            int i = tid / 6, j = tid % 6;
            float s = 0.0f;
            for (int ii = 0; ii < i; ii++)
                for (int jj = 0; jj < j; jj++) s += s25[ii*5 + jj];
            dst[tid] = s;
        }
    } else if (bid < 761) {
        __shared__ unsigned s_k[256];
        int idx = (bid - 450)*256 + tid;
        unsigned k = 0xFFFFFFFFu;
        if (idx < 90*882) k = f2key(w1[idx]);
        s_k[tid] = k;
        __syncthreads();
        for (int s = 128; s > 0; s >>= 1) {
            if (tid < s) { unsigned o = s_k[tid+s]; if (o < s_k[tid]) s_k[tid] = o; }
            __syncthreads();
        }
        if (tid == 0) atomicMin(&g_wmink, s_k[0]);
    } else if (bid < 930) {
        int i = (bid - 761)*256 + tid;
        if (i < NB*90*15*16/16) ((uint4*)g_ft1p)[i] = make_uint4(0,0,0,0);
    } else {
        for (int i = tid; i < NB*90;  i += 256) g_cflag1[i] = 0;
        for (int i = tid; i < NB*250; i += 256) g_cflag2[i] = 0;
        if (tid < NB) { g_any1[tid] = 0; g_any2[tid] = 0; }
    }
}

// ===========================================================================
// conv1 slow path (rare): per-t rescan straight from input. Exact fp32.
__device__ __noinline__ int conv1_slow(const float* __restrict__ inp,
                                       int b, int f, int y, int x,
                                       const float* __restrict__ w1) {
    const float* wf = w1 + (size_t)f*882;
    for (int t = 1; t < 15; t++) {
        const float* pl = inp + ((size_t)(b*NT + t))*18*1024;
        float cum = 0.0f;
        for (int c = 0; c < 18; c++)
            for (int i = 0; i < 7; i++) {
                int h = y + i - 2;
                if ((unsigned)h >= 32u) continue;
                for (int j = 0; j < 7; j++) {
                    int w = x + j - 2;
                    if ((unsigned)w >= 32u) continue;
                    if (pl[(c << 10) + (h << 5) + w] > 0.5f) cum += wf[c*49 + i*7 + j];
                }
            }
        if (cum > 15.0f) return t;
    }
    return 15;
}

// ===========================================================================
// conv1 (R9 proven): one block per batch, thread = pixel. ntaps*wmin bound
// proves ft==0 for all 90 filters at ~all pixels; exceptions exact.
__global__ __launch_bounds__(1024) void k_conv1(const float* __restrict__ inp,
                                                const float* __restrict__ w1) {
    __shared__ uint64_t s_m[18*34];
    __shared__ uint16_t s_nt[960];
    __shared__ uint16_t s_elist[960];
    __shared__ int      s_ne;
    int b = blockIdx.x, tid = threadIdx.x;
    float wmin = key2f(g_wmink);
    if (tid == 0) s_ne = 0;

    if (tid < 612) {
        int c = tid / 34, hh = tid % 34, h = hh - 2;
        uint64_t mask = 0;
        if ((unsigned)h < 32u) {
            const float4* row = (const float4*)(inp + ((size_t)b*NT*18 + c)*1024 + (h << 5));
            uint32_t bits = 0;
#pragma unroll
            for (int k = 0; k < 8; k++) {
                float4 v = row[k];
                bits |= (v.x > 0.5f ? 1u : 0u) << (k*4);
                bits |= (v.y > 0.5f ? 2u : 0u) << (k*4);
                bits |= (v.z > 0.5f ? 4u : 0u) << (k*4);
                bits |= (v.w > 0.5f ? 8u : 0u) << (k*4);
            }
            mask = ((uint64_t)bits) << 2;
        }
        s_m[tid] = mask;
    }
    if (tid < 960) s_nt[tid] = 0;
    __syncthreads();

    int y = tid >> 5, x = tid & 31;
    if (y < 30 && x < 30) {
        int nt = 0;
        for (int c = 0; c < 18; c++) {
            const uint64_t* base = s_m + c*34 + y;
#pragma unroll
            for (int i = 0; i < 7; i++)
                nt += __popc((uint32_t)(base[i] >> x) & 0x7Fu);
        }
        s_nt[tid] = (uint16_t)nt;
        if (!((float)nt * wmin > 15.0f)) {
            int sl = atomicAdd(&s_ne, 1);
            s_elist[sl] = (uint16_t)tid;
        }
    }
    __syncthreads();

    int ne = s_ne;
    for (int base = 0; base < ne; base += 11) {
        int slot = tid / 90, f = tid - slot*90;
        if (slot < 11 && base + slot < ne) {
            int pix = s_elist[base + slot];
            int yy = pix >> 5, xx = pix & 31;
            float pot0 = 0.0f;
            const float* wf = w1 + (size_t)f*882;
            for (int c = 0; c < 18; c++) {
                const uint64_t* mb = s_m + c*34 + yy;
#pragma unroll
                for (int i = 0; i < 7; i++) {
                    uint32_t wnd = (uint32_t)(mb[i] >> xx) & 0x7Fu;
                    const float* wr = wf + c*49 + i*7;
                    while (wnd) {
                        int p = __ffs(wnd) - 1;
                        wnd &= wnd - 1;
                        pot0 += __ldg(wr + p);
                    }
                }
            }
            int ft = (pot0 > 15.0f) ? 0 : conv1_slow(inp, b, f, yy, xx, w1);
            g_excft[((size_t)b*900 + yy*30 + xx)*90 + f] = (int8_t)ft;
        }
        __syncthreads();
    }

    bool nz = false;
    if (ne > 0 && tid < 225) {
        int py = tid / 15, px = tid % 15;
        int m00 = (py*2)*32 + px*2;
        int m01 = m00 + 1, m10 = m00 + 32, m11 = m10 + 1;
        bool e00 = !((float)s_nt[m00]*wmin > 15.0f);
        bool e01 = !((float)s_nt[m01]*wmin > 15.0f);
        bool e10 = !((float)s_nt[m10]*wmin > 15.0f);
        bool e11 = !((float)s_nt[m11]*wmin > 15.0f);
        if (e00 && e01 && e10 && e11) {
            int yy = py*2, xx = px*2;
            const int8_t* q00 = g_excft + ((size_t)b*900 + yy*30     + xx    )*90;
            const int8_t* q01 = g_excft + ((size_t)b*900 + yy*30     + xx + 1)*90;
            const int8_t* q10 = g_excft + ((size_t)b*900 + (yy+1)*30 + xx    )*90;
            const int8_t* q11 = g_excft + ((size_t)b*900 + (yy+1)*30 + xx + 1)*90;
            for (int f = 0; f < 90; f++) {
                int v0 = q00[f], v1 = q01[f], v2 = q10[f], v3 = q11[f];
                int m0 = v0 < v1 ? v0 : v1;
                int m1 = v2 < v3 ? v2 : v3;
                int pv = m0 < m1 ? m0 : m1;
                if (pv) {
                    g_ft1p[((b*90 + f)*15 + py)*16 + px] = (int8_t)pv;
                    g_cflag1[b*90 + f] = 1;
                    nz = true;
                }
            }
        }
    }
    int cnt = __syncthreads_count(nz);
    if (tid == 0 && cnt) atomicAdd(&g_any1[b], 1);
}

// ===========================================================================
// conv2: SAT fast path; slow path via def[15] registers + direct global reads
// of flagged channel rows (no big smem arrays => high occupancy).
// Fused 3x3 pool + layer-2 flags.
__global__ __launch_bounds__(192) void k_conv2(const float* __restrict__ w2) {
    __shared__ float   s_sat[36];
    __shared__ uint8_t s_flags[90];
    __shared__ int8_t  s_ftp[169];
    int tid = threadIdx.x;
    int f = blockIdx.x, b = blockIdx.y;
    int any = g_any1[b];

    if (tid < 36) s_sat[tid] = g_wsat2[f*36 + tid];
    if (any && tid < 90) s_flags[tid] = g_cflag1[b*90 + tid];
    __syncthreads();

    if (tid < 169) {
        int y = tid / 13, x = tid - y*13;
        int r0 = max(0, y-1), r1 = min(14, y+3);
        int c0 = max(0, x-1), c1 = min(14, x+3);
        int i0 = r0 - (y-1), i1 = r1 - (y-1);
        int j0 = c0 - (x-1), j1 = c1 - (x-1);
        float a0 = s_sat[(i1+1)*6 + (j1+1)] - s_sat[i0*6 + (j1+1)]
                 - s_sat[(i1+1)*6 + j0]     + s_sat[i0*6 + j0];
        int ft;
        if (!any) {
            ft = (a0 > 10.0f) ? 0 : 15;
        } else {
            float def[15];
#pragma unroll
            for (int t = 0; t < 15; t++) def[t] = 0.f;
            for (int c = 0; c < 90; c++) {
                if (!s_flags[c]) continue;
                const int8_t* tp = g_ft1p + (size_t)(b*90 + c)*240;
                const float*  wp = w2 + ((size_t)f*90 + c)*25;
                for (int r = r0; r <= r1; r++)
                    for (int cc = c0; cc <= c1; cc++) {
                        int tf = tp[r*16 + cc];
                        if (tf) {
                            float wv = __ldg(wp + (r-(y-1))*5 + (cc-(x-1)));
#pragma unroll
                            for (int t = 0; t < 15; t++) def[t] += (tf > t) ? wv : 0.f;
                        }
                    }
            }
            ft = 15;
#pragma unroll
            for (int t = 14; t >= 0; t--) if (a0 - def[t] > 10.0f) ft = t;
        }
        s_ftp[tid] = (int8_t)ft;
    }
    __syncthreads();

    bool nz = false;
    if (tid < 16) {
        int yy = tid >> 2, xx = tid & 3;
        const int8_t* bp = s_ftp + yy*39 + xx*3;
        int v = 15;
#pragma unroll
        for (int dy = 0; dy < 3; dy++)
#pragma unroll
            for (int dx = 0; dx < 3; dx++) {
                int u = bp[dy*13 + dx];
                v = u < v ? u : v;
            }
        g_ft2p[(b*250 + f)*16 + tid] = (int8_t)v;
        nz = (v != 0);
    }
    int cnt = __syncthreads_count(nz);
    if (tid == 0 && cnt) { g_cflag2[b*250 + f] = 1; atomicAdd(&g_any2[b], 1); }
}

// ===========================================================================
// conv3 (R9 proven): SAT fast path, corrections + histogram otherwise.
__global__ __launch_bounds__(256) void k_conv3(const float* __restrict__ w3,
                                               float* __restrict__ pot) {
    __shared__ __align__(16) int8_t s_tf[250*16];
    __shared__ float   s_sat[16*36];
    __shared__ float   s_h[14*256];
    __shared__ uint8_t s_flags[250];
    int tid = threadIdx.x;
    int fg = blockIdx.x, b = blockIdx.y;
    int any = g_any2[b];

    for (int i = tid; i < 16*36; i += 256) {
        int f = fg*16 + i/36;
        s_sat[i] = (f < 200) ? g_wsat3[f*36 + i%36] : 0.0f;
    }
    if (any) {
        const uint4* src = (const uint4*)(g_ft2p + (size_t)b*250*16);
        for (int i = tid; i < 250; i += 256) ((uint4*)s_tf)[i] = src[i];
        if (tid < 250) s_flags[tid] = g_cflag2[b*250 + tid];
        for (int t = 0; t < 14; t++) s_h[t*256 + tid] = 0.0f;
    }
    __syncthreads();

    int fi = tid >> 4, p = tid & 15;
    int f = fg*16 + fi;
    if (f < 200) {
        int y = p >> 2, x = p & 3;
        int r0 = max(0, y-2), r1 = min(3, y+2);
        int c0 = max(0, x-2), c1 = min(3, x+2);
        int i0 = r0 - (y-2), i1 = r1 - (y-2);
        int j0 = c0 - (x-2), j1 = c1 - (x-2);
        const float* S = s_sat + fi*36;
        float a0 = S[(i1+1)*6 + (j1+1)] - S[i0*6 + (j1+1)]
                 - S[(i1+1)*6 + j0]     + S[i0*6 + j0];
        float* o = pot + ((size_t)b*NT*200 + f)*16 + p;
        if (!any) {
#pragma unroll
            for (int t = 0; t < NT; t++) o[(size_t)t * 3200] = a0;
        } else {
            float* hb = s_h + tid;
            for (int c = 0; c < 250; c++) {
                if (!s_flags[c]) continue;
                const int8_t* tp = s_tf + c*16;
                const float*  wp = w3 + ((size_t)f*250 + c)*25;
                for (int r = r0; r <= r1; r++)
                    for (int cc = c0; cc <= c1; cc++) {
                        int tf = tp[r*4 + cc];
                        if (tf) {
                            float wv = __ldg(wp + (r-(y-2))*5 + (cc-(x-2)));
                            a0 -= wv;
                            if (tf < 15) hb[(tf-1)*256] += wv;
                        }
                    }
            }
            float cum = a0;
#pragma unroll
            for (int t = 0; t < NT; t++) {
                if (t) cum += hb[(t-1)*256];
                o[(size_t)t * 3200] = cum;
            }
        }
    }
}

// ===========================================================================
// winner (proven): argmax over pot3[:,14] > 0, earliest index on ties.
__global__ void k_winner(const float* __restrict__ pot, float* __restrict__ cls) {
    __shared__ float s_v[256];
    __shared__ int   s_i[256];
    int b = blockIdx.x, tid = threadIdx.x;
    const float* p = pot + ((size_t)b*NT + 14) * 3200;
    float bv = 0.0f; int bi = 1 << 30;
    for (int i = tid; i < 3200; i += 256) {
        float v = p[i];
        if (v > bv) { bv = v; bi = i; }
    }
    s_v[tid] = bv; s_i[tid] = bi;
    __syncthreads();
    for (int s = 128; s > 0; s >>= 1) {
        if (tid < s) {
            float ov = s_v[tid+s]; int oi = s_i[tid+s];
            if (ov > s_v[tid] || (ov == s_v[tid] && oi < s_i[tid])) {
                s_v[tid] = ov; s_i[tid] = oi;
            }
        }
        __syncthreads();
    }
    if (tid == 0)
        cls[b] = (s_v[0] > 0.0f) ? (float)((s_i[0] >> 4) / 20) : -1.0f;
}

// ===========================================================================
extern "C" void kernel_launch(void* const* d_in, const int* in_sizes, int n_in,
                              void* d_out, int out_size) {
    const float* inp = (const float*)d_in[0];
    const float* w1  = (const float*)d_in[1];
    const float* w2  = (const float*)d_in[2];
    const float* w3  = (const float*)d_in[3];

    float* out = (float*)d_out;
    float* pot = out;
    float* cls = nullptr;
    if (out_size == NB + NB*NT*3200) {   // (cls, pot3) concatenated
        cls = out;
        pot = out + NB;
    }

    k_prep  <<<931, 256>>>(w1, w2, w3);
    k_conv1 <<<NB, 1024>>>(inp, w1);
    k_conv2 <<<dim3(250, NB), 192>>>(w2);
    k_conv3 <<<dim3(13, NB), 256>>>(w3, pot);
    if (cls) k_winner<<<NB, 256>>>(pot, cls);
}